// round 12
// baseline (speedup 1.0000x reference)
#include <cuda_runtime.h>
#include <cuda_fp16.h>
#include <cstdint>
#include <math.h>

#define N_ROWS 4096
#define HID 512
#define TSTEPS 12
#define KZX 256
#define G3 1536
#define LDW_IH 258

// ---- sgemm_mma (prologue GEMMs) config ----
#define BKC 64                 // K halves per stage
#define STAGE_BYTES 32768
#define NSTAGE 3
#define DSMEM_G (NSTAGE * STAGE_BYTES)

// ---- fused step kernel config ----
#define FS_STAGE (16384 + 3 * 8192)    // A 16KB + 3 gate B sections 8KB = 40960
#define FS_NST 3
#define DSMEM_F (FS_NST * FS_STAGE)    // 122880

// ---------------- device scratch (no allocs allowed) ----------------
__device__ __half g_zx [N_ROWS * KZX];  // concat(z,x), fp16
__device__ __half g_hA [N_ROWS * HID];  // hidden state buffer 0 (fp16)
__device__ __half g_hB [N_ROWS * HID];  // hidden state buffer 1 (fp16)
__device__ float  g_gi [N_ROWS * G3];   // gi_zx precomputed (fp32)
__device__ float  g_x  [N_ROWS * 2];    // initial action (t=0 input)
__device__ __half g_wi [G3 * KZX];      // W_ih[:, :256] repacked, fp16
__device__ __half g_wh [G3 * HID];      // W_hh, fp16
__device__ __half g_wh0[HID * KZX];     // W_h0, fp16
__device__ float  g_wt [G3 * 2];        // W_ih[:, 256:258] packed (fp32)

// ---------------- helpers ----------------
__device__ __forceinline__ float rcp_fast(float v) {
    float r; asm("rcp.approx.f32 %0, %1;" : "=f"(r) : "f"(v));
    return r;
}
__device__ __forceinline__ uint32_t smem_u32(const void* p) {
    uint32_t a;
    asm("{ .reg .u64 t; cvta.to.shared.u64 t, %1; cvt.u32.u64 %0, t; }"
        : "=r"(a) : "l"(p));
    return a;
}
__device__ __forceinline__ uint32_t lds_u32(uint32_t addr) {
    uint32_t v; asm volatile("ld.shared.b32 %0, [%1];" : "=r"(v) : "r"(addr));
    return v;
}
__device__ __forceinline__ void cp16(uint32_t dst, const void* src) {
    asm volatile("cp.async.cg.shared.global [%0], [%1], 16;" :: "r"(dst), "l"(src));
}
__device__ __forceinline__ float fast_sigmoid(float x) {
    return rcp_fast(1.f + __expf(-x));
}
__device__ __forceinline__ float fast_tanh(float x) {
    float t = __expf(-2.f * fabsf(x));
    float m = (1.f - t) * rcp_fast(1.f + t);
    return copysignf(m, x);
}

// ---------------- prologue kernels ----------------
__global__ void zx_kernel(const float* __restrict__ z, const float* __restrict__ x) {
    int i = blockIdx.x * blockDim.x + threadIdx.x;
    if (i >= N_ROWS * 128) return;
    int row = i >> 7, c = i & 127;
    g_zx[row * KZX + c]       = __float2half_rn(z[i]);
    g_zx[row * KZX + 128 + c] = __float2half_rn(x[i]);
}

__global__ void a0_kernel(const float* __restrict__ x0,
                          const float* __restrict__ W_ia,
                          const float* __restrict__ b_ia) {
    int row = blockIdx.x * blockDim.x + threadIdx.x;
    if (row >= N_ROWS) return;
    float v0 = x0[row * 4 + 0], v1 = x0[row * 4 + 1];
    float v2 = x0[row * 4 + 2], v3 = x0[row * 4 + 3];
#pragma unroll
    for (int c = 0; c < 2; ++c) {
        g_x[row * 2 + c] = b_ia[c] + v0 * W_ia[c * 4 + 0] + v1 * W_ia[c * 4 + 1]
                                   + v2 * W_ia[c * 4 + 2] + v3 * W_ia[c * 4 + 3];
    }
}

// One merged pack kernel (also initializes out[] with b_out for the atomics)
#define PK_WI  (G3 * KZX)
#define PK_WH  (PK_WI + G3 * HID)
#define PK_WH0 (PK_WH + HID * KZX)
#define PK_WT  (PK_WH0 + G3 * 2)
#define PK_OUT (PK_WT + N_ROWS * TSTEPS)
__global__ void pack_all(const float* __restrict__ W_ih,
                         const float* __restrict__ W_hh,
                         const float* __restrict__ W_h0,
                         const float* __restrict__ b_out,
                         float* __restrict__ out) {
    int i = blockIdx.x * blockDim.x + threadIdx.x;
    if (i < PK_WI) {
        int r = i >> 8, c = i & 255;
        g_wi[i] = __float2half_rn(W_ih[(size_t)r * LDW_IH + c]);
    } else if (i < PK_WH) {
        int j = i - PK_WI;
        g_wh[j] = __float2half_rn(W_hh[j]);
    } else if (i < PK_WH0) {
        int j = i - PK_WH;
        g_wh0[j] = __float2half_rn(W_h0[j]);
    } else if (i < PK_WT) {
        int j = i - PK_WH0;
        int r = j >> 1, c = j & 1;
        g_wt[j] = W_ih[(size_t)r * LDW_IH + 256 + c];
    } else if (i < PK_OUT) {
        int j = i - PK_WT;                 // (row, t) index
        out[j * 2 + 0] = b_out[0];
        out[j * 2 + 1] = b_out[1];
    }
}

// ---------------------------------------------------------------------------
// fp16 mma.sync GEMM (prologue: h0 and gi). Same as R11.
// ---------------------------------------------------------------------------
__global__ __launch_bounds__(128, 2)
void sgemm_mma(const __half* __restrict__ A, int lda,
               const __half* __restrict__ W, int ldw,
               const float* __restrict__ bias,
               void* __restrict__ Cv, int ldc,
               int K, int out_half)
{
    extern __shared__ char smraw[];
    const int tid = threadIdx.x;
    const int wid = tid >> 5;
    const int lane = tid & 31;
    const int gid = lane >> 2;
    const int tig = lane & 3;
    const int warp_m = wid & 1;
    const int warp_n = wid >> 1;
    const int rowBase = blockIdx.y * 128;
    const int colBase = blockIdx.x * 128;
    const int NK = K / BKC;

    const uint32_t smBase = smem_u32(smraw);

    auto load_stage = [&](int ks, int slot) {
        const int k0 = ks * BKC;
        const uint32_t aOff = smBase + (uint32_t)slot * STAGE_BYTES;
        const uint32_t bOff = aOff + 16384u;
#pragma unroll
        for (int i = 0; i < 8; ++i) {
            int q = tid + i * 128;
            int r = q >> 3;
            int c = q & 7;
            uint32_t d = (uint32_t)(r * 128 + ((c ^ (r & 7)) << 4));
            cp16(aOff + d, A + (size_t)(rowBase + r) * lda + k0 + c * 8);
            cp16(bOff + d, W + (size_t)(colBase + r) * ldw + k0 + c * 8);
        }
        asm volatile("cp.async.commit_group;" ::: "memory");
    };

    float acc[4][8][4];
#pragma unroll
    for (int mt = 0; mt < 4; ++mt)
#pragma unroll
        for (int nt = 0; nt < 8; ++nt)
#pragma unroll
            for (int c = 0; c < 4; ++c) acc[mt][nt][c] = 0.f;

    uint32_t fa[2][4][4], fb[2][8][2];

    auto load_frags = [&](uint32_t aOff, uint32_t bOff, int kk, int buf) {
        const uint32_t c0 = (uint32_t)(((2 * kk)     ^ gid) << 4);
        const uint32_t c1 = (uint32_t)(((2 * kk + 1) ^ gid) << 4);
#pragma unroll
        for (int mt = 0; mt < 4; ++mt) {
            int ar = warp_m * 64 + mt * 16 + gid;
            uint32_t rb = aOff + (uint32_t)(ar * 128) + (uint32_t)(tig * 4);
            fa[buf][mt][0] = lds_u32(rb + c0);
            fa[buf][mt][1] = lds_u32(rb + 8 * 128 + c0);
            fa[buf][mt][2] = lds_u32(rb + c1);
            fa[buf][mt][3] = lds_u32(rb + 8 * 128 + c1);
        }
#pragma unroll
        for (int nt = 0; nt < 8; ++nt) {
            int br = warp_n * 64 + nt * 8 + gid;
            uint32_t rb = bOff + (uint32_t)(br * 128) + (uint32_t)(tig * 4);
            fb[buf][nt][0] = lds_u32(rb + c0);
            fb[buf][nt][1] = lds_u32(rb + c1);
        }
    };

    auto mma_all = [&](int buf) {
#pragma unroll
        for (int mt = 0; mt < 4; ++mt)
#pragma unroll
            for (int nt = 0; nt < 8; ++nt) {
                asm volatile(
                    "mma.sync.aligned.m16n8k16.row.col.f32.f16.f16.f32 "
                    "{%0,%1,%2,%3}, {%4,%5,%6,%7}, {%8,%9}, {%0,%1,%2,%3};"
                    : "+f"(acc[mt][nt][0]), "+f"(acc[mt][nt][1]),
                      "+f"(acc[mt][nt][2]), "+f"(acc[mt][nt][3])
                    : "r"(fa[buf][mt][0]), "r"(fa[buf][mt][1]),
                      "r"(fa[buf][mt][2]), "r"(fa[buf][mt][3]),
                      "r"(fb[buf][nt][0]), "r"(fb[buf][nt][1]));
            }
    };

    load_stage(0, 0);
    load_stage(1, 1);

    for (int ks = 0; ks < NK; ++ks) {
        if (ks + 1 < NK) {
            asm volatile("cp.async.wait_group 1;" ::: "memory");
        } else {
            asm volatile("cp.async.wait_group 0;" ::: "memory");
        }
        __syncthreads();

        const int slot = ks % NSTAGE;
        const uint32_t aOff = smBase + (uint32_t)slot * STAGE_BYTES;
        const uint32_t bOff = aOff + 16384u;

        load_frags(aOff, bOff, 0, 0);
#pragma unroll
        for (int kk = 0; kk < 4; ++kk) {
            if (kk < 3) load_frags(aOff, bOff, kk + 1, (kk + 1) & 1);
            mma_all(kk & 1);
        }
        __syncthreads();

        if (ks + 2 < NK) load_stage(ks + 2, (ks + 2) % NSTAGE);
    }

#pragma unroll
    for (int mt = 0; mt < 4; ++mt) {
        int row = rowBase + warp_m * 64 + mt * 16 + gid;
#pragma unroll
        for (int nt = 0; nt < 8; ++nt) {
            int col = colBase + warp_n * 64 + nt * 8 + tig * 2;
            float b0 = bias[col], b1 = bias[col + 1];
            float2 v0 = make_float2(acc[mt][nt][0] + b0, acc[mt][nt][1] + b1);
            float2 v1 = make_float2(acc[mt][nt][2] + b0, acc[mt][nt][3] + b1);
            if (out_half) {
                __half* C = (__half*)Cv;
                *reinterpret_cast<__half2*>(C + (size_t)row * ldc + col) =
                    __floats2half2_rn(v0.x, v0.y);
                *reinterpret_cast<__half2*>(C + (size_t)(row + 8) * ldc + col) =
                    __floats2half2_rn(v1.x, v1.y);
            } else {
                float* C = (float*)Cv;
                *reinterpret_cast<float2*>(C + (size_t)row * ldc + col) = v0;
                *reinterpret_cast<float2*>(C + (size_t)(row + 8) * ldc + col) = v1;
            }
        }
    }
}

// ---------------------------------------------------------------------------
// Fused step kernel: gh-GEMM (3 gate blocks for the SAME 64 hidden units)
// + GRU cell + output projection, all in one launch.
//   grid (8 unit-groups, 32 row-tiles), 256 threads = 8 warps (4 M x 2 N).
//   CTA: rows [by*128,+128) x hidden units [bx*64,+64), all 3 gates.
//   A = h_in (fp16, [4096,512]); B sections g: W_hh rows g*512 + j0 + [0,64).
//   Epilogue: gh in registers -> gates -> h_out (other buffer) -> per-row
//   output partials -> width-4 shuffle -> atomicAdd into out (pre-biased).
// ---------------------------------------------------------------------------
__global__ __launch_bounds__(256)
void step_fused(const __half* __restrict__ hin,
                __half* __restrict__ hout,
                const float* __restrict__ xsrc, int ldx,
                const float* __restrict__ b_hh,
                const float* __restrict__ W_out,
                float* __restrict__ out, int t)
{
    extern __shared__ char smraw[];
    const int tid = threadIdx.x;
    const int wid = tid >> 5;
    const int lane = tid & 31;
    const int gid = lane >> 2;        // 0..7
    const int tig = lane & 3;         // 0..3
    const int warp_m = wid & 3;       // 4 warps along M (32 rows each)
    const int warp_n = wid >> 2;      // 2 warps along N (32 units each)
    const int rowBase = blockIdx.y * 128;
    const int j0 = blockIdx.x * 64;   // hidden-unit block
    const int NK = HID / 64;          // 8 K-stages of 64 halves

    const uint32_t smBase = smem_u32(smraw);
    const __half* Wh = g_wh;

    // stage loader: A 1024 chunks + B 3x512 chunks (16B each)
    auto load_stage = [&](int ks, int slot) {
        const int k0 = ks * 64;
        const uint32_t aOff = smBase + (uint32_t)slot * FS_STAGE;
        const uint32_t bOff = aOff + 16384u;
#pragma unroll
        for (int i = 0; i < 4; ++i) {          // A: 128 rows x 8 chunks
            int q = tid + i * 256;
            int r = q >> 3, c = q & 7;
            uint32_t d = (uint32_t)(r * 128 + ((c ^ (r & 7)) << 4));
            cp16(aOff + d, hin + (size_t)(rowBase + r) * HID + k0 + c * 8);
        }
#pragma unroll
        for (int i = 0; i < 6; ++i) {          // B: 3 sections x 64 rows x 8 chunks
            int q = tid + i * 256;             // 0..1535
            int sec = q >> 9;                  // gate 0..2
            int rr = (q >> 3) & 63;            // row in section
            int c = q & 7;
            uint32_t d = (uint32_t)(sec * 8192 + rr * 128 + ((c ^ (rr & 7)) << 4));
            cp16(bOff + d, Wh + (size_t)(sec * HID + j0 + rr) * HID + k0 + c * 8);
        }
        asm volatile("cp.async.commit_group;" ::: "memory");
    };

    float acc[3][2][4][4];
#pragma unroll
    for (int g = 0; g < 3; ++g)
#pragma unroll
        for (int mt = 0; mt < 2; ++mt)
#pragma unroll
            for (int nt = 0; nt < 4; ++nt)
#pragma unroll
                for (int c = 0; c < 4; ++c) acc[g][mt][nt][c] = 0.f;

    uint32_t fa[2][2][4], fb[2][3][4][2];

    auto load_frags = [&](uint32_t aOff, uint32_t bOff, int kk, int buf) {
        const uint32_t c0 = (uint32_t)(((2 * kk)     ^ gid) << 4);
        const uint32_t c1 = (uint32_t)(((2 * kk + 1) ^ gid) << 4);
#pragma unroll
        for (int mt = 0; mt < 2; ++mt) {
            int ar = warp_m * 32 + mt * 16 + gid;      // ar&7 == gid
            uint32_t rb = aOff + (uint32_t)(ar * 128) + (uint32_t)(tig * 4);
            fa[buf][mt][0] = lds_u32(rb + c0);
            fa[buf][mt][1] = lds_u32(rb + 8 * 128 + c0);
            fa[buf][mt][2] = lds_u32(rb + c1);
            fa[buf][mt][3] = lds_u32(rb + 8 * 128 + c1);
        }
#pragma unroll
        for (int g = 0; g < 3; ++g)
#pragma unroll
            for (int nt = 0; nt < 4; ++nt) {
                int br = warp_n * 32 + nt * 8 + gid;   // br&7 == gid
                uint32_t rb = bOff + (uint32_t)(g * 8192 + br * 128) + (uint32_t)(tig * 4);
                fb[buf][g][nt][0] = lds_u32(rb + c0);
                fb[buf][g][nt][1] = lds_u32(rb + c1);
            }
    };

    auto mma_all = [&](int buf) {
#pragma unroll
        for (int g = 0; g < 3; ++g)
#pragma unroll
            for (int mt = 0; mt < 2; ++mt)
#pragma unroll
                for (int nt = 0; nt < 4; ++nt) {
                    asm volatile(
                        "mma.sync.aligned.m16n8k16.row.col.f32.f16.f16.f32 "
                        "{%0,%1,%2,%3}, {%4,%5,%6,%7}, {%8,%9}, {%0,%1,%2,%3};"
                        : "+f"(acc[g][mt][nt][0]), "+f"(acc[g][mt][nt][1]),
                          "+f"(acc[g][mt][nt][2]), "+f"(acc[g][mt][nt][3])
                        : "r"(fa[buf][mt][0]), "r"(fa[buf][mt][1]),
                          "r"(fa[buf][mt][2]), "r"(fa[buf][mt][3]),
                          "r"(fb[buf][g][nt][0]), "r"(fb[buf][g][nt][1]));
                }
    };

    load_stage(0, 0);
    load_stage(1, 1);

    for (int ks = 0; ks < NK; ++ks) {
        if (ks + 1 < NK) {
            asm volatile("cp.async.wait_group 1;" ::: "memory");
        } else {
            asm volatile("cp.async.wait_group 0;" ::: "memory");
        }
        __syncthreads();

        const int slot = ks % FS_NST;
        const uint32_t aOff = smBase + (uint32_t)slot * FS_STAGE;
        const uint32_t bOff = aOff + 16384u;

        load_frags(aOff, bOff, 0, 0);
#pragma unroll
        for (int kk = 0; kk < 4; ++kk) {
            if (kk < 3) load_frags(aOff, bOff, kk + 1, (kk + 1) & 1);
            mma_all(kk & 1);
        }
        __syncthreads();

        if (ks + 2 < NK) load_stage(ks + 2, (ks + 2) % FS_NST);
    }

    // ---- fused GRU epilogue ----
    // per-thread rows: ri = mt*2 + rh -> row = rowBase + warp_m*32 + mt*16 + rh*8 + gid
    float xa[4], xb[4];
    int rows[4];
#pragma unroll
    for (int ri = 0; ri < 4; ++ri) {
        rows[ri] = rowBase + warp_m * 32 + (ri >> 1) * 16 + (ri & 1) * 8 + gid;
        xa[ri] = xsrc[(size_t)rows[ri] * ldx + 0];
        xb[ri] = xsrc[(size_t)rows[ri] * ldx + 1];
    }

    float o0[4] = {0.f, 0.f, 0.f, 0.f};
    float o1[4] = {0.f, 0.f, 0.f, 0.f};

#pragma unroll
    for (int nt = 0; nt < 4; ++nt) {
#pragma unroll
        for (int hc = 0; hc < 2; ++hc) {
            int jg = j0 + warp_n * 32 + nt * 8 + tig * 2 + hc;    // global hidden unit
            float wr0 = g_wt[(size_t)jg * 2],            wr1 = g_wt[(size_t)jg * 2 + 1];
            float wz0 = g_wt[(size_t)(HID + jg) * 2],    wz1 = g_wt[(size_t)(HID + jg) * 2 + 1];
            float wn0 = g_wt[(size_t)(2 * HID + jg) * 2], wn1 = g_wt[(size_t)(2 * HID + jg) * 2 + 1];
            float bhr = b_hh[jg], bhz = b_hh[HID + jg], bhn = b_hh[2 * HID + jg];
            float wo0 = W_out[jg], wo1 = W_out[HID + jg];
#pragma unroll
            for (int mt = 0; mt < 2; ++mt)
#pragma unroll
                for (int rh = 0; rh < 2; ++rh) {
                    int ri = mt * 2 + rh;
                    int c = rh * 2 + hc;
                    int row = rows[ri];
                    const float* gir = g_gi + (size_t)row * G3;
                    float gh_r = acc[0][mt][nt][c] + bhr;
                    float gh_z = acc[1][mt][nt][c] + bhz;
                    float gh_n = acc[2][mt][nt][c] + bhn;
                    float gi_r = gir[jg]           + xa[ri] * wr0 + xb[ri] * wr1;
                    float gi_z = gir[HID + jg]     + xa[ri] * wz0 + xb[ri] * wz1;
                    float gi_n = gir[2 * HID + jg] + xa[ri] * wn0 + xb[ri] * wn1;
                    float r = fast_sigmoid(gi_r + gh_r);
                    float u = fast_sigmoid(gi_z + gh_z);
                    float n = fast_tanh(gi_n + r * gh_n);
                    float hold = __half2float(hin[(size_t)row * HID + jg]);
                    float hnew = (1.f - u) * n + u * hold;
                    hout[(size_t)row * HID + jg] = __float2half_rn(hnew);
                    o0[ri] += hnew * wo0;
                    o1[ri] += hnew * wo1;
                }
        }
    }

    // reduce across tig (4 lanes share a row) then atomic-accumulate outputs
#pragma unroll
    for (int ri = 0; ri < 4; ++ri) {
        float v0 = o0[ri], v1 = o1[ri];
        v0 += __shfl_xor_sync(0xffffffffu, v0, 1);
        v0 += __shfl_xor_sync(0xffffffffu, v0, 2);
        v1 += __shfl_xor_sync(0xffffffffu, v1, 1);
        v1 += __shfl_xor_sync(0xffffffffu, v1, 2);
        if (tig == 0) {
            atomicAdd(&out[(size_t)rows[ri] * (TSTEPS * 2) + t * 2 + 0], v0);
            atomicAdd(&out[(size_t)rows[ri] * (TSTEPS * 2) + t * 2 + 1], v1);
        }
    }
}

// ---------------------------------------------------------------------------
// Host launcher
// ---------------------------------------------------------------------------
static void* sym_addr(const void* sym) {
    void* p = nullptr;
    cudaGetSymbolAddress(&p, sym);
    return p;
}

extern "C" void kernel_launch(void* const* d_in, const int* in_sizes, int n_in,
                              void* d_out, int out_size) {
    const float* z     = (const float*)d_in[0];
    const float* x     = (const float*)d_in[1];
    const float* x0    = (const float*)d_in[2];
    const float* W_ia  = (const float*)d_in[3];
    const float* b_ia  = (const float*)d_in[4];
    const float* W_h0  = (const float*)d_in[5];
    const float* b_h0  = (const float*)d_in[6];
    const float* W_ih  = (const float*)d_in[7];
    const float* b_ih  = (const float*)d_in[8];
    const float* W_hh  = (const float*)d_in[9];
    const float* b_hh  = (const float*)d_in[10];
    const float* W_out = (const float*)d_in[11];
    const float* b_out = (const float*)d_in[12];
    float* out = (float*)d_out;

    __half* p_zx  = (__half*)sym_addr(g_zx);
    __half* p_hA  = (__half*)sym_addr(g_hA);
    __half* p_hB  = (__half*)sym_addr(g_hB);
    float*  p_gi  = (float*)sym_addr(g_gi);
    float*  p_x   = (float*)sym_addr(g_x);
    __half* p_wi  = (__half*)sym_addr(g_wi);
    __half* p_wh0 = (__half*)sym_addr(g_wh0);

    cudaFuncSetAttribute(sgemm_mma, cudaFuncAttributeMaxDynamicSharedMemorySize, DSMEM_G);
    cudaFuncSetAttribute(step_fused, cudaFuncAttributeMaxDynamicSharedMemorySize, DSMEM_F);

    // prologue (3 launches; out[] pre-filled with b_out for atomics)
    zx_kernel<<<(N_ROWS * 128 + 255) / 256, 256>>>(z, x);
    a0_kernel<<<(N_ROWS + 255) / 256, 256>>>(x0, W_ia, b_ia);
    pack_all<<<(PK_OUT + 255) / 256, 256>>>(W_ih, W_hh, W_h0, b_out, out);

    // h0 = zx @ W_h0.T + b_h0   [4096, 512], fp16 out -> buffer A
    sgemm_mma<<<dim3(HID / 128, N_ROWS / 128), 128, DSMEM_G>>>(
        p_zx, KZX, p_wh0, KZX, b_h0, p_hA, HID, KZX, 1);
    // gi = zx @ W_ih[:,:256].T + b_ih   [4096, 1536], fp32 out
    sgemm_mma<<<dim3(G3 / 128, N_ROWS / 128), 128, DSMEM_G>>>(
        p_zx, KZX, p_wi, KZX, b_ih, p_gi, G3, KZX, 0);

    // fused recurrent steps (h double-buffered; x from previous step's out)
    for (int t = 0; t < TSTEPS; ++t) {
        const __half* hin = (t & 1) ? p_hB : p_hA;
        __half* hout      = (t & 1) ? p_hA : p_hB;
        const float* xsrc = (t == 0) ? p_x : (out + (t - 1) * 2);
        int ldx           = (t == 0) ? 2 : (TSTEPS * 2);
        step_fused<<<dim3(64 / 64 * 8, N_ROWS / 128), 256, DSMEM_F>>>(
            hin, hout, xsrc, ldx, b_hh, W_out, out, t);
    }
}

// round 13
// speedup vs baseline: 1.2237x; 1.2237x over previous
#include <cuda_runtime.h>
#include <cuda_fp16.h>
#include <cstdint>
#include <math.h>

#define N_ROWS 4096
#define HID 512
#define TSTEPS 12
#define KZX 256
#define G3 1536
#define LDW_IH 258
#define BKC 64                 // K halves per stage
#define STAGE_BYTES 32768      // A 16KB + B 16KB
#define NSTAGE 3
#define DSMEM (NSTAGE * STAGE_BYTES)   // 96 KB -> 2 CTAs/SM

// ---------------- device scratch (no allocs allowed) ----------------
__device__ __half g_zx [N_ROWS * KZX];  // concat(z,x), fp16
__device__ __half g_h  [N_ROWS * HID];  // hidden state, fp16
__device__ float  g_gi [N_ROWS * G3];   // gi_zx precomputed (fp32)
__device__ __half g_gh [N_ROWS * G3];   // gh per step (fp16, bias included)
__device__ float  g_x  [N_ROWS * 2];    // current action
__device__ __half g_wi [G3 * KZX];      // W_ih[:, :256] repacked, fp16
__device__ __half g_wh [G3 * HID];      // W_hh, fp16
__device__ __half g_wh0[HID * KZX];     // W_h0, fp16
__device__ float  g_wt [G3 * 2];        // W_ih[:, 256:258] packed (fp32)

// ---------------- helpers ----------------
__device__ __forceinline__ float rcp_fast(float v) {
    float r; asm("rcp.approx.f32 %0, %1;" : "=f"(r) : "f"(v));
    return r;
}
__device__ __forceinline__ uint32_t smem_u32(const void* p) {
    uint32_t a;
    asm("{ .reg .u64 t; cvta.to.shared.u64 t, %1; cvt.u32.u64 %0, t; }"
        : "=r"(a) : "l"(p));
    return a;
}
__device__ __forceinline__ uint32_t lds_u32(uint32_t addr) {
    uint32_t v; asm volatile("ld.shared.b32 %0, [%1];" : "=r"(v) : "r"(addr));
    return v;
}
__device__ __forceinline__ void cp16(uint32_t dst, const void* src) {
    asm volatile("cp.async.cg.shared.global [%0], [%1], 16;" :: "r"(dst), "l"(src));
}

// ---------------- prologue kernels ----------------
__global__ void zx_kernel(const float* __restrict__ z, const float* __restrict__ x) {
    int i = blockIdx.x * blockDim.x + threadIdx.x;
    if (i >= N_ROWS * 128) return;
    int row = i >> 7, c = i & 127;
    g_zx[row * KZX + c]       = __float2half_rn(z[i]);
    g_zx[row * KZX + 128 + c] = __float2half_rn(x[i]);
}

__global__ void a0_kernel(const float* __restrict__ x0,
                          const float* __restrict__ W_ia,
                          const float* __restrict__ b_ia) {
    int row = blockIdx.x * blockDim.x + threadIdx.x;
    if (row >= N_ROWS) return;
    float v0 = x0[row * 4 + 0], v1 = x0[row * 4 + 1];
    float v2 = x0[row * 4 + 2], v3 = x0[row * 4 + 3];
#pragma unroll
    for (int c = 0; c < 2; ++c) {
        g_x[row * 2 + c] = b_ia[c] + v0 * W_ia[c * 4 + 0] + v1 * W_ia[c * 4 + 1]
                                   + v2 * W_ia[c * 4 + 2] + v3 * W_ia[c * 4 + 3];
    }
}

#define PK_WI  (G3 * KZX)
#define PK_WH  (PK_WI + G3 * HID)
#define PK_WH0 (PK_WH + HID * KZX)
#define PK_WT  (PK_WH0 + G3 * 2)
__global__ void pack_all(const float* __restrict__ W_ih,
                         const float* __restrict__ W_hh,
                         const float* __restrict__ W_h0) {
    int i = blockIdx.x * blockDim.x + threadIdx.x;
    if (i < PK_WI) {
        int r = i >> 8, c = i & 255;
        g_wi[i] = __float2half_rn(W_ih[(size_t)r * LDW_IH + c]);
    } else if (i < PK_WH) {
        int j = i - PK_WI;
        g_wh[j] = __float2half_rn(W_hh[j]);
    } else if (i < PK_WH0) {
        int j = i - PK_WH;
        g_wh0[j] = __float2half_rn(W_h0[j]);
    } else if (i < PK_WT) {
        int j = i - PK_WH0;
        int r = j >> 1, c = j & 1;
        g_wt[j] = W_ih[(size_t)r * LDW_IH + 256 + c];
    }
}

// ---------------------------------------------------------------------------
// fp16 mma.sync GEMM:  C[4096, M_out] = A[4096, K] @ W[M_out, K]^T + bias
// CTA 128x128, 256 threads = 8 warps (2 M x 4 N), warp tile 64x32 m16n8k16.
// 3-stage BK=64 cp.async pipeline, XOR-swizzled smem, single-buffered frags
// (fits 128 regs -> 2 CTAs/SM = 16 warps/SM for latency hiding).
// out_half: 1 -> fp16 C (h0, gh paths); 0 -> fp32 C (gi).
// ---------------------------------------------------------------------------
__global__ __launch_bounds__(256, 2)
void sgemm_mma(const __half* __restrict__ A, int lda,
               const __half* __restrict__ W, int ldw,
               const float* __restrict__ bias,
               void* __restrict__ Cv, int ldc,
               int K, int out_half)
{
    extern __shared__ char smraw[];
    const int tid = threadIdx.x;
    const int wid = tid >> 5;
    const int lane = tid & 31;
    const int gid = lane >> 2;        // 0..7
    const int tig = lane & 3;         // 0..3
    const int warp_m = wid & 1;       // 2 warps along M (64 rows)
    const int warp_n = wid >> 1;      // 4 warps along N (32 cols)
    const int rowBase = blockIdx.y * 128;
    const int colBase = blockIdx.x * 128;
    const int NK = K / BKC;

    const uint32_t smBase = smem_u32(smraw);

    // stage loader: per operand 128 rows x 8 chunks(16B); 4 chunks/thread
    auto load_stage = [&](int ks, int slot) {
        const int k0 = ks * BKC;
        const uint32_t aOff = smBase + (uint32_t)slot * STAGE_BYTES;
        const uint32_t bOff = aOff + 16384u;
#pragma unroll
        for (int i = 0; i < 4; ++i) {
            int q = tid + i * 256;        // 0..1023
            int r = q >> 3;               // 0..127
            int c = q & 7;                // chunk
            uint32_t d = (uint32_t)(r * 128 + ((c ^ (r & 7)) << 4));
            cp16(aOff + d, A + (size_t)(rowBase + r) * lda + k0 + c * 8);
            cp16(bOff + d, W + (size_t)(colBase + r) * ldw + k0 + c * 8);
        }
        asm volatile("cp.async.commit_group;" ::: "memory");
    };

    float acc[4][4][4];
#pragma unroll
    for (int mt = 0; mt < 4; ++mt)
#pragma unroll
        for (int nt = 0; nt < 4; ++nt)
#pragma unroll
            for (int c = 0; c < 4; ++c) acc[mt][nt][c] = 0.f;

    load_stage(0, 0);
    load_stage(1, 1);

    for (int ks = 0; ks < NK; ++ks) {
        if (ks + 1 < NK) {
            asm volatile("cp.async.wait_group 1;" ::: "memory");
        } else {
            asm volatile("cp.async.wait_group 0;" ::: "memory");
        }
        __syncthreads();

        const int slot = ks % NSTAGE;
        const uint32_t aOff = smBase + (uint32_t)slot * STAGE_BYTES;
        const uint32_t bOff = aOff + 16384u;

#pragma unroll
        for (int kk = 0; kk < 4; ++kk) {
            const uint32_t c0 = (uint32_t)(((2 * kk)     ^ gid) << 4);
            const uint32_t c1 = (uint32_t)(((2 * kk + 1) ^ gid) << 4);
            uint32_t fa[4][4], fb[4][2];
#pragma unroll
            for (int mt = 0; mt < 4; ++mt) {
                int ar = warp_m * 64 + mt * 16 + gid;      // ar&7 == gid
                uint32_t rb = aOff + (uint32_t)(ar * 128) + (uint32_t)(tig * 4);
                fa[mt][0] = lds_u32(rb + c0);
                fa[mt][1] = lds_u32(rb + 8 * 128 + c0);
                fa[mt][2] = lds_u32(rb + c1);
                fa[mt][3] = lds_u32(rb + 8 * 128 + c1);
            }
#pragma unroll
            for (int nt = 0; nt < 4; ++nt) {
                int br = warp_n * 32 + nt * 8 + gid;       // br&7 == gid
                uint32_t rb = bOff + (uint32_t)(br * 128) + (uint32_t)(tig * 4);
                fb[nt][0] = lds_u32(rb + c0);
                fb[nt][1] = lds_u32(rb + c1);
            }
#pragma unroll
            for (int mt = 0; mt < 4; ++mt)
#pragma unroll
                for (int nt = 0; nt < 4; ++nt) {
                    asm volatile(
                        "mma.sync.aligned.m16n8k16.row.col.f32.f16.f16.f32 "
                        "{%0,%1,%2,%3}, {%4,%5,%6,%7}, {%8,%9}, {%0,%1,%2,%3};"
                        : "+f"(acc[mt][nt][0]), "+f"(acc[mt][nt][1]),
                          "+f"(acc[mt][nt][2]), "+f"(acc[mt][nt][3])
                        : "r"(fa[mt][0]), "r"(fa[mt][1]),
                          "r"(fa[mt][2]), "r"(fa[mt][3]),
                          "r"(fb[nt][0]), "r"(fb[nt][1]));
                }
        }
        __syncthreads();

        if (ks + 2 < NK) load_stage(ks + 2, (ks + 2) % NSTAGE);
    }

    // epilogue: bias add, fp16 or fp32 store
#pragma unroll
    for (int mt = 0; mt < 4; ++mt) {
        int row = rowBase + warp_m * 64 + mt * 16 + gid;
#pragma unroll
        for (int nt = 0; nt < 4; ++nt) {
            int col = colBase + warp_n * 32 + nt * 8 + tig * 2;
            float b0 = bias[col], b1 = bias[col + 1];
            float2 v0 = make_float2(acc[mt][nt][0] + b0, acc[mt][nt][1] + b1);
            float2 v1 = make_float2(acc[mt][nt][2] + b0, acc[mt][nt][3] + b1);
            if (out_half) {
                __half* C = (__half*)Cv;
                *reinterpret_cast<__half2*>(C + (size_t)row * ldc + col) =
                    __floats2half2_rn(v0.x, v0.y);
                *reinterpret_cast<__half2*>(C + (size_t)(row + 8) * ldc + col) =
                    __floats2half2_rn(v1.x, v1.y);
            } else {
                float* C = (float*)Cv;
                *reinterpret_cast<float2*>(C + (size_t)row * ldc + col) = v0;
                *reinterpret_cast<float2*>(C + (size_t)(row + 8) * ldc + col) = v1;
            }
        }
    }
}

// ---------------------------------------------------------------------------
// Fused gate math + hidden update + output projection.
// 2 rows per 256-thread block; gh read as fp16.
// ---------------------------------------------------------------------------
__device__ __forceinline__ float fast_sigmoid(float x) {
    return rcp_fast(1.f + __expf(-x));
}
__device__ __forceinline__ float fast_tanh(float x) {
    float t = __expf(-2.f * fabsf(x));
    float m = (1.f - t) * rcp_fast(1.f + t);
    return copysignf(m, x);
}
__device__ __forceinline__ void ld_half4(const __half* p, float* dst) {
    uint2 raw = *reinterpret_cast<const uint2*>(p);
    float2 p0 = __half22float2(*reinterpret_cast<__half2*>(&raw.x));
    float2 p1 = __half22float2(*reinterpret_cast<__half2*>(&raw.y));
    dst[0] = p0.x; dst[1] = p0.y; dst[2] = p1.x; dst[3] = p1.y;
}

__global__ __launch_bounds__(256)
void gate_kernel(const float* __restrict__ W_out,
                 const float* __restrict__ b_out,
                 float* __restrict__ out, int t) {
    int tid = threadIdx.x;
    int row = blockIdx.x * 2 + (tid >> 7);
    int wt = tid & 127;
    float xa = g_x[row * 2 + 0];
    float xb = g_x[row * 2 + 1];

    int j0 = wt * 4;
    const float*  gi = &g_gi[(size_t)row * G3];
    const __half* gh = &g_gh[(size_t)row * G3];

    float gir[4], giz[4], gin[4], ghr[4], ghz[4], ghn[4], hv[4];
    *reinterpret_cast<float4*>(gir) = *reinterpret_cast<const float4*>(&gi[j0]);
    *reinterpret_cast<float4*>(giz) = *reinterpret_cast<const float4*>(&gi[512 + j0]);
    *reinterpret_cast<float4*>(gin) = *reinterpret_cast<const float4*>(&gi[1024 + j0]);
    ld_half4(gh + j0, ghr);
    ld_half4(gh + 512 + j0, ghz);
    ld_half4(gh + 1024 + j0, ghn);
    ld_half4(&g_h[(size_t)row * HID + j0], hv);

    float wr[8], wz[8], wn[8];
    *reinterpret_cast<float4*>(&wr[0]) = *reinterpret_cast<const float4*>(&g_wt[(size_t)j0 * 2]);
    *reinterpret_cast<float4*>(&wr[4]) = *reinterpret_cast<const float4*>(&g_wt[(size_t)j0 * 2 + 4]);
    *reinterpret_cast<float4*>(&wz[0]) = *reinterpret_cast<const float4*>(&g_wt[(size_t)(512 + j0) * 2]);
    *reinterpret_cast<float4*>(&wz[4]) = *reinterpret_cast<const float4*>(&g_wt[(size_t)(512 + j0) * 2 + 4]);
    *reinterpret_cast<float4*>(&wn[0]) = *reinterpret_cast<const float4*>(&g_wt[(size_t)(1024 + j0) * 2]);
    *reinterpret_cast<float4*>(&wn[4]) = *reinterpret_cast<const float4*>(&g_wt[(size_t)(1024 + j0) * 2 + 4]);

    float o0 = 0.f, o1 = 0.f;
    float hn[4];
#pragma unroll
    for (int i = 0; i < 4; ++i) {
        int j = j0 + i;
        float gi_r = gir[i] + xa * wr[i * 2] + xb * wr[i * 2 + 1];
        float gi_z = giz[i] + xa * wz[i * 2] + xb * wz[i * 2 + 1];
        float gi_n = gin[i] + xa * wn[i * 2] + xb * wn[i * 2 + 1];
        float r = fast_sigmoid(gi_r + ghr[i]);
        float u = fast_sigmoid(gi_z + ghz[i]);
        float n = fast_tanh(gi_n + r * ghn[i]);
        float h_new = (1.f - u) * n + u * hv[i];
        hn[i] = h_new;
        o0 += h_new * W_out[j];
        o1 += h_new * W_out[HID + j];
    }
    {
        __half2 p0 = __floats2half2_rn(hn[0], hn[1]);
        __half2 p1 = __floats2half2_rn(hn[2], hn[3]);
        uint2 hraw;
        hraw.x = *reinterpret_cast<uint32_t*>(&p0);
        hraw.y = *reinterpret_cast<uint32_t*>(&p1);
        *reinterpret_cast<uint2*>(&g_h[(size_t)row * HID + j0]) = hraw;
    }

    unsigned m = 0xffffffffu;
#pragma unroll
    for (int off = 16; off; off >>= 1) {
        o0 += __shfl_down_sync(m, o0, off);
        o1 += __shfl_down_sync(m, o1, off);
    }
    __shared__ float s0[8], s1[8];
    int wi = tid >> 5, lane = tid & 31;
    if (lane == 0) { s0[wi] = o0; s1[wi] = o1; }
    __syncthreads();
    if (wt == 0) {
        int base = (tid >> 7) * 4;
        float r0 = s0[base] + s0[base + 1] + s0[base + 2] + s0[base + 3] + b_out[0];
        float r1 = s1[base] + s1[base + 1] + s1[base + 2] + s1[base + 3] + b_out[1];
        out[row * (TSTEPS * 2) + t * 2 + 0] = r0;
        out[row * (TSTEPS * 2) + t * 2 + 1] = r1;
        g_x[row * 2 + 0] = r0;
        g_x[row * 2 + 1] = r1;
    }
}

// ---------------------------------------------------------------------------
// Host launcher
// ---------------------------------------------------------------------------
static void* sym_addr(const void* sym) {
    void* p = nullptr;
    cudaGetSymbolAddress(&p, sym);
    return p;
}

extern "C" void kernel_launch(void* const* d_in, const int* in_sizes, int n_in,
                              void* d_out, int out_size) {
    const float* z     = (const float*)d_in[0];
    const float* x     = (const float*)d_in[1];
    const float* x0    = (const float*)d_in[2];
    const float* W_ia  = (const float*)d_in[3];
    const float* b_ia  = (const float*)d_in[4];
    const float* W_h0  = (const float*)d_in[5];
    const float* b_h0  = (const float*)d_in[6];
    const float* W_ih  = (const float*)d_in[7];
    const float* b_ih  = (const float*)d_in[8];
    const float* W_hh  = (const float*)d_in[9];
    const float* b_hh  = (const float*)d_in[10];
    const float* W_out = (const float*)d_in[11];
    const float* b_out = (const float*)d_in[12];
    float* out = (float*)d_out;

    __half* p_zx  = (__half*)sym_addr(g_zx);
    __half* p_h   = (__half*)sym_addr(g_h);
    float*  p_gi  = (float*)sym_addr(g_gi);
    __half* p_gh  = (__half*)sym_addr(g_gh);
    __half* p_wi  = (__half*)sym_addr(g_wi);
    __half* p_wh  = (__half*)sym_addr(g_wh);
    __half* p_wh0 = (__half*)sym_addr(g_wh0);

    cudaFuncSetAttribute(sgemm_mma, cudaFuncAttributeMaxDynamicSharedMemorySize, DSMEM);

    // prologue
    zx_kernel<<<(N_ROWS * 128 + 255) / 256, 256>>>(z, x);
    a0_kernel<<<(N_ROWS + 255) / 256, 256>>>(x0, W_ia, b_ia);
    pack_all<<<(PK_WT + 255) / 256, 256>>>(W_ih, W_hh, W_h0);

    // h0 = zx @ W_h0.T + b_h0   [4096, 512], fp16 out
    sgemm_mma<<<dim3(HID / 128, N_ROWS / 128), 256, DSMEM>>>(
        p_zx, KZX, p_wh0, KZX, b_h0, p_h, HID, KZX, 1);
    // gi = zx @ W_ih[:,:256].T + b_ih   [4096, 1536], fp32 out
    sgemm_mma<<<dim3(G3 / 128, N_ROWS / 128), 256, DSMEM>>>(
        p_zx, KZX, p_wi, KZX, b_ih, p_gi, G3, KZX, 0);

    // recurrent steps (gh written fp16, bias included)
    for (int t = 0; t < TSTEPS; ++t) {
        sgemm_mma<<<dim3(G3 / 128, N_ROWS / 128), 256, DSMEM>>>(
            p_h, HID, p_wh, HID, b_hh, p_gh, G3, HID, 1);
        gate_kernel<<<N_ROWS / 2, 256>>>(W_out, b_out, out, t);
    }
}

// round 14
// speedup vs baseline: 1.2947x; 1.0580x over previous
#include <cuda_runtime.h>
#include <cuda_fp16.h>
#include <cstdint>
#include <math.h>

#define N_ROWS 4096
#define HID 512
#define TSTEPS 12
#define KZX 256
#define G3 1536
#define LDW_IH 258
#define BKC 64                 // K (halves) per stage
#define STAGE_BYTES 32768      // A 16KB + B 16KB per stage
#define NSTAGE 3
#define DSMEM (NSTAGE * STAGE_BYTES)

// ---------------- device scratch (no allocs allowed) ----------------
__device__ __half g_zx [N_ROWS * KZX];  // concat(z,x), fp16
__device__ __half g_h  [N_ROWS * HID];  // hidden state, fp16
__device__ __half g_gi [N_ROWS * G3];   // gi_zx precomputed (fp16, bias incl.)
__device__ __half g_gh [N_ROWS * G3];   // gh per step (fp16, bias incl.)
__device__ float  g_x  [N_ROWS * 2];    // current action
__device__ __half g_wi [G3 * KZX];      // W_ih[:, :256] repacked, fp16
__device__ __half g_wh [G3 * HID];      // W_hh, fp16
__device__ __half g_wh0[HID * KZX];     // W_h0, fp16
__device__ float  g_wt [G3 * 2];        // W_ih[:, 256:258] packed (fp32)

// ---------------- helpers ----------------
__device__ __forceinline__ float rcp_fast(float v) {
    float r; asm("rcp.approx.f32 %0, %1;" : "=f"(r) : "f"(v));
    return r;
}
__device__ __forceinline__ uint32_t smem_u32(const void* p) {
    uint32_t a;
    asm("{ .reg .u64 t; cvta.to.shared.u64 t, %1; cvt.u32.u64 %0, t; }"
        : "=r"(a) : "l"(p));
    return a;
}
__device__ __forceinline__ uint32_t lds_u32(uint32_t addr) {
    uint32_t v; asm volatile("ld.shared.b32 %0, [%1];" : "=r"(v) : "r"(addr));
    return v;
}
__device__ __forceinline__ void cp16(uint32_t dst, const void* src) {
    asm volatile("cp.async.cg.shared.global [%0], [%1], 16;" :: "r"(dst), "l"(src));
}

// ---------------- prologue kernels ----------------
__global__ void zx_kernel(const float* __restrict__ z, const float* __restrict__ x) {
    int i = blockIdx.x * blockDim.x + threadIdx.x;
    if (i >= N_ROWS * 128) return;
    int row = i >> 7, c = i & 127;
    g_zx[row * KZX + c]       = __float2half_rn(z[i]);
    g_zx[row * KZX + 128 + c] = __float2half_rn(x[i]);
}

__global__ void a0_kernel(const float* __restrict__ x0,
                          const float* __restrict__ W_ia,
                          const float* __restrict__ b_ia) {
    int row = blockIdx.x * blockDim.x + threadIdx.x;
    if (row >= N_ROWS) return;
    float v0 = x0[row * 4 + 0], v1 = x0[row * 4 + 1];
    float v2 = x0[row * 4 + 2], v3 = x0[row * 4 + 3];
#pragma unroll
    for (int c = 0; c < 2; ++c) {
        g_x[row * 2 + c] = b_ia[c] + v0 * W_ia[c * 4 + 0] + v1 * W_ia[c * 4 + 1]
                                   + v2 * W_ia[c * 4 + 2] + v3 * W_ia[c * 4 + 3];
    }
}

#define PK_WI  (G3 * KZX)
#define PK_WH  (PK_WI + G3 * HID)
#define PK_WH0 (PK_WH + HID * KZX)
#define PK_WT  (PK_WH0 + G3 * 2)
__global__ void pack_all(const float* __restrict__ W_ih,
                         const float* __restrict__ W_hh,
                         const float* __restrict__ W_h0) {
    int i = blockIdx.x * blockDim.x + threadIdx.x;
    if (i < PK_WI) {
        int r = i >> 8, c = i & 255;
        g_wi[i] = __float2half_rn(W_ih[(size_t)r * LDW_IH + c]);
    } else if (i < PK_WH) {
        int j = i - PK_WI;
        g_wh[j] = __float2half_rn(W_hh[j]);
    } else if (i < PK_WH0) {
        int j = i - PK_WH;
        g_wh0[j] = __float2half_rn(W_h0[j]);
    } else if (i < PK_WT) {
        int j = i - PK_WH0;
        int r = j >> 1, c = j & 1;
        g_wt[j] = W_ih[(size_t)r * LDW_IH + 256 + c];
    }
}

// ---------------------------------------------------------------------------
// fp16 mma.sync GEMM (R11-proven core):
//   C[4096, M_out] = A[4096, K] @ W[M_out, K]^T + bias     (C in fp16)
// CTA 128x128, 4 warps (2x2), warp tile 64x64 via m16n8k16.
// BK=64 halves per stage, 3-stage cp.async pipeline, XOR-swizzled smem,
// double-buffered register fragments (hides 29-cyc LDS latency).
// ---------------------------------------------------------------------------
__global__ __launch_bounds__(128, 2)
void sgemm_mma(const __half* __restrict__ A, int lda,
               const __half* __restrict__ W, int ldw,
               const float* __restrict__ bias,
               __half* __restrict__ C, int ldc,
               int K)
{
    extern __shared__ char smraw[];
    const int tid = threadIdx.x;
    const int wid = tid >> 5;
    const int lane = tid & 31;
    const int gid = lane >> 2;
    const int tig = lane & 3;
    const int warp_m = wid & 1;
    const int warp_n = wid >> 1;
    const int rowBase = blockIdx.y * 128;
    const int colBase = blockIdx.x * 128;
    const int NK = K / BKC;

    const uint32_t smBase = smem_u32(smraw);

    auto load_stage = [&](int ks, int slot) {
        const int k0 = ks * BKC;
        const uint32_t aOff = smBase + (uint32_t)slot * STAGE_BYTES;
        const uint32_t bOff = aOff + 16384u;
#pragma unroll
        for (int i = 0; i < 8; ++i) {
            int q = tid + i * 128;
            int r = q >> 3;
            int c = q & 7;
            uint32_t d = (uint32_t)(r * 128 + ((c ^ (r & 7)) << 4));
            cp16(aOff + d, A + (size_t)(rowBase + r) * lda + k0 + c * 8);
            cp16(bOff + d, W + (size_t)(colBase + r) * ldw + k0 + c * 8);
        }
        asm volatile("cp.async.commit_group;" ::: "memory");
    };

    float acc[4][8][4];
#pragma unroll
    for (int mt = 0; mt < 4; ++mt)
#pragma unroll
        for (int nt = 0; nt < 8; ++nt)
#pragma unroll
            for (int c = 0; c < 4; ++c) acc[mt][nt][c] = 0.f;

    uint32_t fa[2][4][4], fb[2][8][2];

    auto load_frags = [&](uint32_t aOff, uint32_t bOff, int kk, int buf) {
        const uint32_t c0 = (uint32_t)(((2 * kk)     ^ gid) << 4);
        const uint32_t c1 = (uint32_t)(((2 * kk + 1) ^ gid) << 4);
#pragma unroll
        for (int mt = 0; mt < 4; ++mt) {
            int ar = warp_m * 64 + mt * 16 + gid;
            uint32_t rb = aOff + (uint32_t)(ar * 128) + (uint32_t)(tig * 4);
            fa[buf][mt][0] = lds_u32(rb + c0);
            fa[buf][mt][1] = lds_u32(rb + 8 * 128 + c0);
            fa[buf][mt][2] = lds_u32(rb + c1);
            fa[buf][mt][3] = lds_u32(rb + 8 * 128 + c1);
        }
#pragma unroll
        for (int nt = 0; nt < 8; ++nt) {
            int br = warp_n * 64 + nt * 8 + gid;
            uint32_t rb = bOff + (uint32_t)(br * 128) + (uint32_t)(tig * 4);
            fb[buf][nt][0] = lds_u32(rb + c0);
            fb[buf][nt][1] = lds_u32(rb + c1);
        }
    };

    auto mma_all = [&](int buf) {
#pragma unroll
        for (int mt = 0; mt < 4; ++mt)
#pragma unroll
            for (int nt = 0; nt < 8; ++nt) {
                asm volatile(
                    "mma.sync.aligned.m16n8k16.row.col.f32.f16.f16.f32 "
                    "{%0,%1,%2,%3}, {%4,%5,%6,%7}, {%8,%9}, {%0,%1,%2,%3};"
                    : "+f"(acc[mt][nt][0]), "+f"(acc[mt][nt][1]),
                      "+f"(acc[mt][nt][2]), "+f"(acc[mt][nt][3])
                    : "r"(fa[buf][mt][0]), "r"(fa[buf][mt][1]),
                      "r"(fa[buf][mt][2]), "r"(fa[buf][mt][3]),
                      "r"(fb[buf][nt][0]), "r"(fb[buf][nt][1]));
            }
    };

    load_stage(0, 0);
    load_stage(1, 1);

    for (int ks = 0; ks < NK; ++ks) {
        if (ks + 1 < NK) {
            asm volatile("cp.async.wait_group 1;" ::: "memory");
        } else {
            asm volatile("cp.async.wait_group 0;" ::: "memory");
        }
        __syncthreads();

        const int slot = ks % NSTAGE;
        const uint32_t aOff = smBase + (uint32_t)slot * STAGE_BYTES;
        const uint32_t bOff = aOff + 16384u;

        load_frags(aOff, bOff, 0, 0);
#pragma unroll
        for (int kk = 0; kk < 4; ++kk) {
            if (kk < 3) load_frags(aOff, bOff, kk + 1, (kk + 1) & 1);
            mma_all(kk & 1);
        }
        __syncthreads();

        if (ks + 2 < NK) load_stage(ks + 2, (ks + 2) % NSTAGE);
    }

    // epilogue: bias add, fp16 stores
#pragma unroll
    for (int mt = 0; mt < 4; ++mt) {
        int row = rowBase + warp_m * 64 + mt * 16 + gid;
#pragma unroll
        for (int nt = 0; nt < 8; ++nt) {
            int col = colBase + warp_n * 64 + nt * 8 + tig * 2;
            float b0 = bias[col], b1 = bias[col + 1];
            *reinterpret_cast<__half2*>(C + (size_t)row * ldc + col) =
                __floats2half2_rn(acc[mt][nt][0] + b0, acc[mt][nt][1] + b1);
            *reinterpret_cast<__half2*>(C + (size_t)(row + 8) * ldc + col) =
                __floats2half2_rn(acc[mt][nt][2] + b0, acc[mt][nt][3] + b1);
        }
    }
}

// ---------------------------------------------------------------------------
// Fused gate math + hidden update + output projection.
// 2 rows per 256-thread block; gi and gh read as fp16 (bias pre-folded).
// ---------------------------------------------------------------------------
__device__ __forceinline__ float fast_sigmoid(float x) {
    return rcp_fast(1.f + __expf(-x));
}
__device__ __forceinline__ float fast_tanh(float x) {
    float t = __expf(-2.f * fabsf(x));
    float m = (1.f - t) * rcp_fast(1.f + t);
    return copysignf(m, x);
}
__device__ __forceinline__ void ld_half4(const __half* p, float* dst) {
    uint2 raw = *reinterpret_cast<const uint2*>(p);
    float2 p0 = __half22float2(*reinterpret_cast<__half2*>(&raw.x));
    float2 p1 = __half22float2(*reinterpret_cast<__half2*>(&raw.y));
    dst[0] = p0.x; dst[1] = p0.y; dst[2] = p1.x; dst[3] = p1.y;
}

__global__ __launch_bounds__(256)
void gate_kernel(const float* __restrict__ W_out,
                 const float* __restrict__ b_out,
                 float* __restrict__ out, int t) {
    int tid = threadIdx.x;
    int row = blockIdx.x * 2 + (tid >> 7);
    int wt = tid & 127;
    float xa = g_x[row * 2 + 0];
    float xb = g_x[row * 2 + 1];

    int j0 = wt * 4;
    const __half* gi = &g_gi[(size_t)row * G3];
    const __half* gh = &g_gh[(size_t)row * G3];

    float gir[4], giz[4], gin[4], ghr[4], ghz[4], ghn[4], hv[4];
    ld_half4(gi + j0, gir);
    ld_half4(gi + 512 + j0, giz);
    ld_half4(gi + 1024 + j0, gin);
    ld_half4(gh + j0, ghr);
    ld_half4(gh + 512 + j0, ghz);
    ld_half4(gh + 1024 + j0, ghn);
    ld_half4(&g_h[(size_t)row * HID + j0], hv);

    float wr[8], wz[8], wn[8];
    *reinterpret_cast<float4*>(&wr[0]) = *reinterpret_cast<const float4*>(&g_wt[(size_t)j0 * 2]);
    *reinterpret_cast<float4*>(&wr[4]) = *reinterpret_cast<const float4*>(&g_wt[(size_t)j0 * 2 + 4]);
    *reinterpret_cast<float4*>(&wz[0]) = *reinterpret_cast<const float4*>(&g_wt[(size_t)(512 + j0) * 2]);
    *reinterpret_cast<float4*>(&wz[4]) = *reinterpret_cast<const float4*>(&g_wt[(size_t)(512 + j0) * 2 + 4]);
    *reinterpret_cast<float4*>(&wn[0]) = *reinterpret_cast<const float4*>(&g_wt[(size_t)(1024 + j0) * 2]);
    *reinterpret_cast<float4*>(&wn[4]) = *reinterpret_cast<const float4*>(&g_wt[(size_t)(1024 + j0) * 2 + 4]);

    float o0 = 0.f, o1 = 0.f;
    float hn[4];
#pragma unroll
    for (int i = 0; i < 4; ++i) {
        int j = j0 + i;
        float gi_r = gir[i] + xa * wr[i * 2] + xb * wr[i * 2 + 1];
        float gi_z = giz[i] + xa * wz[i * 2] + xb * wz[i * 2 + 1];
        float gi_n = gin[i] + xa * wn[i * 2] + xb * wn[i * 2 + 1];
        float r = fast_sigmoid(gi_r + ghr[i]);
        float u = fast_sigmoid(gi_z + ghz[i]);
        float n = fast_tanh(gi_n + r * ghn[i]);
        float h_new = (1.f - u) * n + u * hv[i];
        hn[i] = h_new;
        o0 += h_new * W_out[j];
        o1 += h_new * W_out[HID + j];
    }
    {
        __half2 p0 = __floats2half2_rn(hn[0], hn[1]);
        __half2 p1 = __floats2half2_rn(hn[2], hn[3]);
        uint2 hraw;
        hraw.x = *reinterpret_cast<uint32_t*>(&p0);
        hraw.y = *reinterpret_cast<uint32_t*>(&p1);
        *reinterpret_cast<uint2*>(&g_h[(size_t)row * HID + j0]) = hraw;
    }

    unsigned m = 0xffffffffu;
#pragma unroll
    for (int off = 16; off; off >>= 1) {
        o0 += __shfl_down_sync(m, o0, off);
        o1 += __shfl_down_sync(m, o1, off);
    }
    __shared__ float s0[8], s1[8];
    int wi = tid >> 5, lane = tid & 31;
    if (lane == 0) { s0[wi] = o0; s1[wi] = o1; }
    __syncthreads();
    if (wt == 0) {
        int base = (tid >> 7) * 4;
        float r0 = s0[base] + s0[base + 1] + s0[base + 2] + s0[base + 3] + b_out[0];
        float r1 = s1[base] + s1[base + 1] + s1[base + 2] + s1[base + 3] + b_out[1];
        out[row * (TSTEPS * 2) + t * 2 + 0] = r0;
        out[row * (TSTEPS * 2) + t * 2 + 1] = r1;
        g_x[row * 2 + 0] = r0;
        g_x[row * 2 + 1] = r1;
    }
}

// ---------------------------------------------------------------------------
// Host launcher
// ---------------------------------------------------------------------------
static void* sym_addr(const void* sym) {
    void* p = nullptr;
    cudaGetSymbolAddress(&p, sym);
    return p;
}

extern "C" void kernel_launch(void* const* d_in, const int* in_sizes, int n_in,
                              void* d_out, int out_size) {
    const float* z     = (const float*)d_in[0];
    const float* x     = (const float*)d_in[1];
    const float* x0    = (const float*)d_in[2];
    const float* W_ia  = (const float*)d_in[3];
    const float* b_ia  = (const float*)d_in[4];
    const float* W_h0  = (const float*)d_in[5];
    const float* b_h0  = (const float*)d_in[6];
    const float* W_ih  = (const float*)d_in[7];
    const float* b_ih  = (const float*)d_in[8];
    const float* W_hh  = (const float*)d_in[9];
    const float* b_hh  = (const float*)d_in[10];
    const float* W_out = (const float*)d_in[11];
    const float* b_out = (const float*)d_in[12];
    float* out = (float*)d_out;

    __half* p_zx  = (__half*)sym_addr(g_zx);
    __half* p_h   = (__half*)sym_addr(g_h);
    __half* p_gi  = (__half*)sym_addr(g_gi);
    __half* p_gh  = (__half*)sym_addr(g_gh);
    __half* p_wi  = (__half*)sym_addr(g_wi);
    __half* p_wh  = (__half*)sym_addr(g_wh);
    __half* p_wh0 = (__half*)sym_addr(g_wh0);

    cudaFuncSetAttribute(sgemm_mma, cudaFuncAttributeMaxDynamicSharedMemorySize, DSMEM);

    // prologue
    zx_kernel<<<(N_ROWS * 128 + 255) / 256, 256>>>(z, x);
    a0_kernel<<<(N_ROWS + 255) / 256, 256>>>(x0, W_ia, b_ia);
    pack_all<<<(PK_WT + 255) / 256, 256>>>(W_ih, W_hh, W_h0);

    // h0 = zx @ W_h0.T + b_h0   [4096, 512], fp16 out
    sgemm_mma<<<dim3(HID / 128, N_ROWS / 128), 128, DSMEM>>>(
        p_zx, KZX, p_wh0, KZX, b_h0, p_h, HID, KZX);
    // gi = zx @ W_ih[:,:256].T + b_ih   [4096, 1536], fp16 out
    sgemm_mma<<<dim3(G3 / 128, N_ROWS / 128), 128, DSMEM>>>(
        p_zx, KZX, p_wi, KZX, b_ih, p_gi, G3, KZX);

    // recurrent steps (gh fp16, bias included)
    for (int t = 0; t < TSTEPS; ++t) {
        sgemm_mma<<<dim3(G3 / 128, N_ROWS / 128), 128, DSMEM>>>(
            p_h, HID, p_wh, HID, b_hh, p_gh, G3, HID);
        gate_kernel<<<N_ROWS / 2, 256>>>(W_out, b_out, out, t);
    }
}

// round 15
// speedup vs baseline: 1.3459x; 1.0396x over previous
#include <cuda_runtime.h>
#include <cuda_fp16.h>
#include <cstdint>
#include <math.h>

#define N_ROWS 4096
#define HID 512
#define TSTEPS 12
#define KZX 256
#define G3 1536
#define LDW_IH 258
#define BKC 64                 // K (halves) per stage
#define STAGE_BYTES 32768      // A 16KB + B 16KB per stage
#define NSTAGE 3
#define DSMEM (NSTAGE * STAGE_BYTES)

// ---------------- device scratch (no allocs allowed) ----------------
__device__ __half g_zx [N_ROWS * KZX];  // concat(z,x), fp16
__device__ __half g_h  [N_ROWS * HID];  // hidden state, fp16
__device__ __half g_gi [N_ROWS * G3];   // gi_zx precomputed (fp16, bias incl.)
__device__ __half g_gh [N_ROWS * G3];   // gh per step (fp16, bias incl.)
__device__ float  g_x  [N_ROWS * 2];    // current action
__device__ __half g_wi [G3 * KZX];      // W_ih[:, :256] repacked, fp16
__device__ __half g_wh [G3 * HID];      // W_hh, fp16
__device__ __half g_wh0[HID * KZX];     // W_h0, fp16
__device__ float  g_wt [G3 * 2];        // W_ih[:, 256:258] packed (fp32)

// ---------------- helpers ----------------
__device__ __forceinline__ float rcp_fast(float v) {
    float r; asm("rcp.approx.f32 %0, %1;" : "=f"(r) : "f"(v));
    return r;
}
__device__ __forceinline__ uint32_t smem_u32(const void* p) {
    uint32_t a;
    asm("{ .reg .u64 t; cvta.to.shared.u64 t, %1; cvt.u32.u64 %0, t; }"
        : "=r"(a) : "l"(p));
    return a;
}
__device__ __forceinline__ void cp16(uint32_t dst, const void* src) {
    asm volatile("cp.async.cg.shared.global [%0], [%1], 16;" :: "r"(dst), "l"(src));
}
__device__ __forceinline__ void ldsm4(uint32_t addr, uint32_t& r0, uint32_t& r1,
                                      uint32_t& r2, uint32_t& r3) {
    asm volatile("ldmatrix.sync.aligned.m8n8.x4.shared.b16 {%0,%1,%2,%3}, [%4];"
                 : "=r"(r0), "=r"(r1), "=r"(r2), "=r"(r3) : "r"(addr));
}

// ---------------- prologue kernels ----------------
__global__ void zx_kernel(const float* __restrict__ z, const float* __restrict__ x) {
    int i = blockIdx.x * blockDim.x + threadIdx.x;
    if (i >= N_ROWS * 128) return;
    int row = i >> 7, c = i & 127;
    g_zx[row * KZX + c]       = __float2half_rn(z[i]);
    g_zx[row * KZX + 128 + c] = __float2half_rn(x[i]);
}

__global__ void a0_kernel(const float* __restrict__ x0,
                          const float* __restrict__ W_ia,
                          const float* __restrict__ b_ia) {
    int row = blockIdx.x * blockDim.x + threadIdx.x;
    if (row >= N_ROWS) return;
    float v0 = x0[row * 4 + 0], v1 = x0[row * 4 + 1];
    float v2 = x0[row * 4 + 2], v3 = x0[row * 4 + 3];
#pragma unroll
    for (int c = 0; c < 2; ++c) {
        g_x[row * 2 + c] = b_ia[c] + v0 * W_ia[c * 4 + 0] + v1 * W_ia[c * 4 + 1]
                                   + v2 * W_ia[c * 4 + 2] + v3 * W_ia[c * 4 + 3];
    }
}

#define PK_WI  (G3 * KZX)
#define PK_WH  (PK_WI + G3 * HID)
#define PK_WH0 (PK_WH + HID * KZX)
#define PK_WT  (PK_WH0 + G3 * 2)
__global__ void pack_all(const float* __restrict__ W_ih,
                         const float* __restrict__ W_hh,
                         const float* __restrict__ W_h0) {
    int i = blockIdx.x * blockDim.x + threadIdx.x;
    if (i < PK_WI) {
        int r = i >> 8, c = i & 255;
        g_wi[i] = __float2half_rn(W_ih[(size_t)r * LDW_IH + c]);
    } else if (i < PK_WH) {
        int j = i - PK_WI;
        g_wh[j] = __float2half_rn(W_hh[j]);
    } else if (i < PK_WH0) {
        int j = i - PK_WH;
        g_wh0[j] = __float2half_rn(W_h0[j]);
    } else if (i < PK_WT) {
        int j = i - PK_WH0;
        int r = j >> 1, c = j & 1;
        g_wt[j] = W_ih[(size_t)r * LDW_IH + 256 + c];
    }
}

// ---------------------------------------------------------------------------
// fp16 mma.sync GEMM:
//   C[4096, M_out] = A[4096, K] @ W[M_out, K]^T + bias     (C in fp16)
// CTA 128x128, 4 warps (2x2), warp tile 64x64 via m16n8k16.
// BK=64 per stage, 3-stage cp.async ring, XOR-swizzled smem, ldmatrix.x4
// fragment loads, double-buffered fragments, ONE __syncthreads per stage
// with the next-stage prefetch issued BEFORE compute.
// ---------------------------------------------------------------------------
__global__ __launch_bounds__(128, 2)
void sgemm_mma(const __half* __restrict__ A, int lda,
               const __half* __restrict__ W, int ldw,
               const float* __restrict__ bias,
               __half* __restrict__ C, int ldc,
               int K)
{
    extern __shared__ char smraw[];
    const int tid = threadIdx.x;
    const int wid = tid >> 5;
    const int lane = tid & 31;
    const int gid = lane >> 2;
    const int tig = lane & 3;
    const int warp_m = wid & 1;
    const int warp_n = wid >> 1;
    const int rowBase = blockIdx.y * 128;
    const int colBase = blockIdx.x * 128;
    const int NK = K / BKC;

    const uint32_t smBase = smem_u32(smraw);

    // ldmatrix per-lane geometry: m = lane>>3 (matrix index within x4)
    const int rl   = lane & 7;          // row within 8-row group
    const int am8  = (lane >> 3) & 1;   // m&1
    const int ksel = lane >> 4;         // m>>1
    // A: matrix m -> rows (+8 if m&1), k-chunk (+1 if m>>1)
    uint32_t aRowB[4];
#pragma unroll
    for (int mt = 0; mt < 4; ++mt)
        aRowB[mt] = (uint32_t)((warp_m * 64 + mt * 16 + rl + am8 * 8) * 128);
    // B: matrix m -> nt (+1 if m>>1), k-chunk (+1 if m&1)
    uint32_t bRowB[4];
#pragma unroll
    for (int g = 0; g < 4; ++g)
        bRowB[g] = (uint32_t)((warp_n * 64 + (2 * g + ksel) * 8 + rl) * 128);

    auto load_stage = [&](int ks, int slot) {
        const int k0 = ks * BKC;
        const uint32_t aOff = smBase + (uint32_t)slot * STAGE_BYTES;
        const uint32_t bOff = aOff + 16384u;
#pragma unroll
        for (int i = 0; i < 8; ++i) {
            int q = tid + i * 128;
            int r = q >> 3;
            int c = q & 7;
            uint32_t d = (uint32_t)(r * 128 + ((c ^ (r & 7)) << 4));
            cp16(aOff + d, A + (size_t)(rowBase + r) * lda + k0 + c * 8);
            cp16(bOff + d, W + (size_t)(colBase + r) * ldw + k0 + c * 8);
        }
        asm volatile("cp.async.commit_group;" ::: "memory");
    };

    float acc[4][8][4];
#pragma unroll
    for (int mt = 0; mt < 4; ++mt)
#pragma unroll
        for (int nt = 0; nt < 8; ++nt)
#pragma unroll
            for (int c = 0; c < 4; ++c) acc[mt][nt][c] = 0.f;

    uint32_t fa[2][4][4], fb[2][8][2];

    auto load_frags = [&](uint32_t aOff, uint32_t bOff, int kk, int buf) {
        const uint32_t cA = (uint32_t)(((2 * kk + ksel) ^ rl) << 4);
        const uint32_t cB = (uint32_t)(((2 * kk + am8) ^ rl) << 4);
#pragma unroll
        for (int mt = 0; mt < 4; ++mt)
            ldsm4(aOff + aRowB[mt] + cA,
                  fa[buf][mt][0], fa[buf][mt][1], fa[buf][mt][2], fa[buf][mt][3]);
#pragma unroll
        for (int g = 0; g < 4; ++g)
            ldsm4(bOff + bRowB[g] + cB,
                  fb[buf][2 * g][0], fb[buf][2 * g][1],
                  fb[buf][2 * g + 1][0], fb[buf][2 * g + 1][1]);
    };

    auto mma_all = [&](int buf) {
#pragma unroll
        for (int mt = 0; mt < 4; ++mt)
#pragma unroll
            for (int nt = 0; nt < 8; ++nt) {
                asm volatile(
                    "mma.sync.aligned.m16n8k16.row.col.f32.f16.f16.f32 "
                    "{%0,%1,%2,%3}, {%4,%5,%6,%7}, {%8,%9}, {%0,%1,%2,%3};"
                    : "+f"(acc[mt][nt][0]), "+f"(acc[mt][nt][1]),
                      "+f"(acc[mt][nt][2]), "+f"(acc[mt][nt][3])
                    : "r"(fa[buf][mt][0]), "r"(fa[buf][mt][1]),
                      "r"(fa[buf][mt][2]), "r"(fa[buf][mt][3]),
                      "r"(fb[buf][nt][0]), "r"(fb[buf][nt][1]));
            }
    };

    load_stage(0, 0);
    load_stage(1, 1);

    for (int ks = 0; ks < NK; ++ks) {
        if (ks + 1 < NK) {
            asm volatile("cp.async.wait_group 1;" ::: "memory");
        } else {
            asm volatile("cp.async.wait_group 0;" ::: "memory");
        }
        // This sync also proves all warps finished reading stage ks-1
        // (= slot (ks+2)%3), so the prefetch below cannot clobber live data.
        __syncthreads();

        if (ks + 2 < NK) load_stage(ks + 2, (ks + 2) % NSTAGE);

        const int slot = ks % NSTAGE;
        const uint32_t aOff = smBase + (uint32_t)slot * STAGE_BYTES;
        const uint32_t bOff = aOff + 16384u;

        load_frags(aOff, bOff, 0, 0);
#pragma unroll
        for (int kk = 0; kk < 4; ++kk) {
            if (kk < 3) load_frags(aOff, bOff, kk + 1, (kk + 1) & 1);
            mma_all(kk & 1);
        }
        // no trailing __syncthreads: next iteration's leading sync covers it
    }

    // epilogue: bias add, fp16 stores
#pragma unroll
    for (int mt = 0; mt < 4; ++mt) {
        int row = rowBase + warp_m * 64 + mt * 16 + gid;
#pragma unroll
        for (int nt = 0; nt < 8; ++nt) {
            int col = colBase + warp_n * 64 + nt * 8 + tig * 2;
            float b0 = bias[col], b1 = bias[col + 1];
            *reinterpret_cast<__half2*>(C + (size_t)row * ldc + col) =
                __floats2half2_rn(acc[mt][nt][0] + b0, acc[mt][nt][1] + b1);
            *reinterpret_cast<__half2*>(C + (size_t)(row + 8) * ldc + col) =
                __floats2half2_rn(acc[mt][nt][2] + b0, acc[mt][nt][3] + b1);
        }
    }
}

// ---------------------------------------------------------------------------
// Fused gate math + hidden update + output projection.
// 2 rows per 256-thread block; gi and gh read as fp16 (bias pre-folded).
// ---------------------------------------------------------------------------
__device__ __forceinline__ float fast_sigmoid(float x) {
    return rcp_fast(1.f + __expf(-x));
}
__device__ __forceinline__ float fast_tanh(float x) {
    float t = __expf(-2.f * fabsf(x));
    float m = (1.f - t) * rcp_fast(1.f + t);
    return copysignf(m, x);
}
__device__ __forceinline__ void ld_half4(const __half* p, float* dst) {
    uint2 raw = *reinterpret_cast<const uint2*>(p);
    float2 p0 = __half22float2(*reinterpret_cast<__half2*>(&raw.x));
    float2 p1 = __half22float2(*reinterpret_cast<__half2*>(&raw.y));
    dst[0] = p0.x; dst[1] = p0.y; dst[2] = p1.x; dst[3] = p1.y;
}

__global__ __launch_bounds__(256)
void gate_kernel(const float* __restrict__ W_out,
                 const float* __restrict__ b_out,
                 float* __restrict__ out, int t) {
    int tid = threadIdx.x;
    int row = blockIdx.x * 2 + (tid >> 7);
    int wt = tid & 127;
    float xa = g_x[row * 2 + 0];
    float xb = g_x[row * 2 + 1];

    int j0 = wt * 4;
    const __half* gi = &g_gi[(size_t)row * G3];
    const __half* gh = &g_gh[(size_t)row * G3];

    float gir[4], giz[4], gin[4], ghr[4], ghz[4], ghn[4], hv[4];
    ld_half4(gi + j0, gir);
    ld_half4(gi + 512 + j0, giz);
    ld_half4(gi + 1024 + j0, gin);
    ld_half4(gh + j0, ghr);
    ld_half4(gh + 512 + j0, ghz);
    ld_half4(gh + 1024 + j0, ghn);
    ld_half4(&g_h[(size_t)row * HID + j0], hv);

    float wr[8], wz[8], wn[8];
    *reinterpret_cast<float4*>(&wr[0]) = *reinterpret_cast<const float4*>(&g_wt[(size_t)j0 * 2]);
    *reinterpret_cast<float4*>(&wr[4]) = *reinterpret_cast<const float4*>(&g_wt[(size_t)j0 * 2 + 4]);
    *reinterpret_cast<float4*>(&wz[0]) = *reinterpret_cast<const float4*>(&g_wt[(size_t)(512 + j0) * 2]);
    *reinterpret_cast<float4*>(&wz[4]) = *reinterpret_cast<const float4*>(&g_wt[(size_t)(512 + j0) * 2 + 4]);
    *reinterpret_cast<float4*>(&wn[0]) = *reinterpret_cast<const float4*>(&g_wt[(size_t)(1024 + j0) * 2]);
    *reinterpret_cast<float4*>(&wn[4]) = *reinterpret_cast<const float4*>(&g_wt[(size_t)(1024 + j0) * 2 + 4]);

    float o0 = 0.f, o1 = 0.f;
    float hn[4];
#pragma unroll
    for (int i = 0; i < 4; ++i) {
        int j = j0 + i;
        float gi_r = gir[i] + xa * wr[i * 2] + xb * wr[i * 2 + 1];
        float gi_z = giz[i] + xa * wz[i * 2] + xb * wz[i * 2 + 1];
        float gi_n = gin[i] + xa * wn[i * 2] + xb * wn[i * 2 + 1];
        float r = fast_sigmoid(gi_r + ghr[i]);
        float u = fast_sigmoid(gi_z + ghz[i]);
        float n = fast_tanh(gi_n + r * ghn[i]);
        float h_new = (1.f - u) * n + u * hv[i];
        hn[i] = h_new;
        o0 += h_new * W_out[j];
        o1 += h_new * W_out[HID + j];
    }
    {
        __half2 p0 = __floats2half2_rn(hn[0], hn[1]);
        __half2 p1 = __floats2half2_rn(hn[2], hn[3]);
        uint2 hraw;
        hraw.x = *reinterpret_cast<uint32_t*>(&p0);
        hraw.y = *reinterpret_cast<uint32_t*>(&p1);
        *reinterpret_cast<uint2*>(&g_h[(size_t)row * HID + j0]) = hraw;
    }

    unsigned m = 0xffffffffu;
#pragma unroll
    for (int off = 16; off; off >>= 1) {
        o0 += __shfl_down_sync(m, o0, off);
        o1 += __shfl_down_sync(m, o1, off);
    }
    __shared__ float s0[8], s1[8];
    int wi = tid >> 5, lane = tid & 31;
    if (lane == 0) { s0[wi] = o0; s1[wi] = o1; }
    __syncthreads();
    if (wt == 0) {
        int base = (tid >> 7) * 4;
        float r0 = s0[base] + s0[base + 1] + s0[base + 2] + s0[base + 3] + b_out[0];
        float r1 = s1[base] + s1[base + 1] + s1[base + 2] + s1[base + 3] + b_out[1];
        out[row * (TSTEPS * 2) + t * 2 + 0] = r0;
        out[row * (TSTEPS * 2) + t * 2 + 1] = r1;
        g_x[row * 2 + 0] = r0;
        g_x[row * 2 + 1] = r1;
    }
}

// ---------------------------------------------------------------------------
// Host launcher
// ---------------------------------------------------------------------------
static void* sym_addr(const void* sym) {
    void* p = nullptr;
    cudaGetSymbolAddress(&p, sym);
    return p;
}

extern "C" void kernel_launch(void* const* d_in, const int* in_sizes, int n_in,
                              void* d_out, int out_size) {
    const float* z     = (const float*)d_in[0];
    const float* x     = (const float*)d_in[1];
    const float* x0    = (const float*)d_in[2];
    const float* W_ia  = (const float*)d_in[3];
    const float* b_ia  = (const float*)d_in[4];
    const float* W_h0  = (const float*)d_in[5];
    const float* b_h0  = (const float*)d_in[6];
    const float* W_ih  = (const float*)d_in[7];
    const float* b_ih  = (const float*)d_in[8];
    const float* W_hh  = (const float*)d_in[9];
    const float* b_hh  = (const float*)d_in[10];
    const float* W_out = (const float*)d_in[11];
    const float* b_out = (const float*)d_in[12];
    float* out = (float*)d_out;

    __half* p_zx  = (__half*)sym_addr(g_zx);
    __half* p_h   = (__half*)sym_addr(g_h);
    __half* p_gi  = (__half*)sym_addr(g_gi);
    __half* p_gh  = (__half*)sym_addr(g_gh);
    __half* p_wi  = (__half*)sym_addr(g_wi);
    __half* p_wh  = (__half*)sym_addr(g_wh);
    __half* p_wh0 = (__half*)sym_addr(g_wh0);

    cudaFuncSetAttribute(sgemm_mma, cudaFuncAttributeMaxDynamicSharedMemorySize, DSMEM);

    // prologue
    zx_kernel<<<(N_ROWS * 128 + 255) / 256, 256>>>(z, x);
    a0_kernel<<<(N_ROWS + 255) / 256, 256>>>(x0, W_ia, b_ia);
    pack_all<<<(PK_WT + 255) / 256, 256>>>(W_ih, W_hh, W_h0);

    // h0 = zx @ W_h0.T + b_h0   [4096, 512], fp16 out
    sgemm_mma<<<dim3(HID / 128, N_ROWS / 128), 128, DSMEM>>>(
        p_zx, KZX, p_wh0, KZX, b_h0, p_h, HID, KZX);
    // gi = zx @ W_ih[:,:256].T + b_ih   [4096, 1536], fp16 out
    sgemm_mma<<<dim3(G3 / 128, N_ROWS / 128), 128, DSMEM>>>(
        p_zx, KZX, p_wi, KZX, b_ih, p_gi, G3, KZX);

    // recurrent steps (gh fp16, bias included)
    for (int t = 0; t < TSTEPS; ++t) {
        sgemm_mma<<<dim3(G3 / 128, N_ROWS / 128), 128, DSMEM>>>(
            p_h, HID, p_wh, HID, b_hh, p_gh, G3, HID);
        gate_kernel<<<N_ROWS / 2, 256>>>(W_out, b_out, out, t);
    }
}